// round 1
// baseline (speedup 1.0000x reference)
#include <cuda_runtime.h>

#define N_NODES 50000
#define N_EDGES 1600000
#define BATCH   1024
#define HIDDEN  256
#define OUTF    64

// ---------------- scratch (device globals: no allocation allowed) ------------
__device__ float g_h   [N_NODES*OUTF];   // transformed node features [N,64]
__device__ float g_as4 [N_NODES*4];      // per-node src scores [N,4]
__device__ float g_ad4 [N_NODES*4];      // per-node dst scores [N,4]
__device__ float g_hout[N_NODES*OUTF];   // aggregated output [N,64]
__device__ int   g_cnt [N_NODES];
__device__ int   g_off [N_NODES+1];
__device__ int   g_cur [N_NODES];
__device__ int   g_esrc[N_EDGES];        // CSR-by-dst source ids
__device__ float g_msg [BATCH*OUTF];     // msg_emb [B,64]
__device__ float g_lse [BATCH];

__device__ __forceinline__ float lrelu(float x) { return fmaxf(x, 0.2f*x); }

// ---------------- init ------------------------------------------------------
__global__ void k_init() {
  int i = blockIdx.x*blockDim.x + threadIdx.x;
  if (i < N_NODES) g_cnt[i] = 0;
}

// ---------------- node transform: h = x @ gat_w ; a_s, a_d ------------------
// block = 256 threads = 4 nodes x 64 features
__global__ void k_node(const float* __restrict__ x, const float* __restrict__ gw,
                       const float* __restrict__ aw_s, const float* __restrict__ aw_d) {
  __shared__ float sw[256];
  __shared__ float satt[128];
  __shared__ float sx[16];
  int tid = threadIdx.x;
  sw[tid] = gw[tid];
  if (tid < 64)       satt[tid]    = aw_s[tid];
  else if (tid < 128) satt[tid]    = aw_d[tid-64];
  int n0 = blockIdx.x*4;
  if (tid < 16) sx[tid] = x[n0*4 + tid];
  __syncthreads();
  int local = tid >> 6;        // node within block
  int j     = tid & 63;        // output feature (head = j/16, f = j%16)
  int node  = n0 + local;
  float h = sx[local*4+0]*sw[j]      + sx[local*4+1]*sw[64+j]
          + sx[local*4+2]*sw[128+j]  + sx[local*4+3]*sw[192+j];
  g_h[node*64 + j] = h;
  float ps = h*satt[j];
  float pd = h*satt[64+j];
  #pragma unroll
  for (int off = 8; off > 0; off >>= 1) {
    ps += __shfl_xor_sync(0xffffffffu, ps, off);
    pd += __shfl_xor_sync(0xffffffffu, pd, off);
  }
  if ((j & 15) == 0) {
    int head = j >> 4;
    g_as4[node*4+head] = ps;
    g_ad4[node*4+head] = pd;
  }
}

// ---------------- CSR build -------------------------------------------------
__global__ void k_hist(const int* __restrict__ ei) {
  int i = blockIdx.x*blockDim.x + threadIdx.x;
  if (i < N_EDGES) atomicAdd(&g_cnt[ei[N_EDGES + i]], 1);
}

__global__ void k_scan() {  // single block, 1024 threads: exclusive scan of g_cnt
  __shared__ int wsum[32];
  __shared__ int wexcl[32];
  __shared__ int s_run;
  int tid = threadIdx.x;
  int lane = tid & 31, wid = tid >> 5;
  if (tid == 0) s_run = 0;
  __syncthreads();
  for (int base = 0; base < N_NODES; base += 1024) {
    int i = base + tid;
    int v = (i < N_NODES) ? g_cnt[i] : 0;
    int incl = v;
    #pragma unroll
    for (int off = 1; off < 32; off <<= 1) {
      int t = __shfl_up_sync(0xffffffffu, incl, off);
      if (lane >= off) incl += t;
    }
    if (lane == 31) wsum[wid] = incl;
    __syncthreads();
    if (wid == 0) {
      int wv = wsum[lane];
      int winc = wv;
      #pragma unroll
      for (int off = 1; off < 32; off <<= 1) {
        int t = __shfl_up_sync(0xffffffffu, winc, off);
        if (lane >= off) winc += t;
      }
      wexcl[lane] = winc - wv;
      if (lane == 31) wsum[0] = winc;   // chunk total
    }
    __syncthreads();
    int excl = s_run + wexcl[wid] + (incl - v);
    if (i < N_NODES) { g_off[i] = excl; g_cur[i] = excl; }
    int tot = wsum[0];
    __syncthreads();
    if (tid == 0) s_run += tot;
    __syncthreads();
  }
  if (tid == 0) g_off[N_NODES] = s_run;
}

__global__ void k_scatter(const int* __restrict__ ei) {
  int i = blockIdx.x*blockDim.x + threadIdx.x;
  if (i < N_EDGES) {
    int d = ei[N_EDGES + i];
    int pos = atomicAdd(&g_cur[d], 1);
    g_esrc[pos] = ei[i];
  }
}

// ---------------- per-node softmax + aggregation (one warp / node) ----------
__global__ void k_agg(const float* __restrict__ gat_b) {
  int gwarp = (blockIdx.x*blockDim.x + threadIdx.x) >> 5;
  int lane  = threadIdx.x & 31;
  if (gwarp >= N_NODES) return;
  int n   = gwarp;
  int beg = g_off[n];
  int end = g_off[n+1];
  float4 ad = *(const float4*)&g_ad4[n*4];

  // phase A: online max / sum-exp per head, lanes stride edges
  float m0=-1e30f,m1=-1e30f,m2=-1e30f,m3=-1e30f;
  float s0=0.f,s1=0.f,s2=0.f,s3=0.f;
  for (int i = beg + lane; i < end; i += 32) {
    int src = g_esrc[i];
    float4 as = *(const float4*)&g_as4[src*4];
    float e0 = lrelu(as.x+ad.x), e1 = lrelu(as.y+ad.y);
    float e2 = lrelu(as.z+ad.z), e3 = lrelu(as.w+ad.w);
    float nm;
    nm = fmaxf(m0,e0); s0 = s0*__expf(m0-nm) + __expf(e0-nm); m0 = nm;
    nm = fmaxf(m1,e1); s1 = s1*__expf(m1-nm) + __expf(e1-nm); m1 = nm;
    nm = fmaxf(m2,e2); s2 = s2*__expf(m2-nm) + __expf(e2-nm); m2 = nm;
    nm = fmaxf(m3,e3); s3 = s3*__expf(m3-nm) + __expf(e3-nm); m3 = nm;
  }
  #pragma unroll
  for (int off = 16; off > 0; off >>= 1) {
    float om, os, nm;
    om = __shfl_xor_sync(0xffffffffu, m0, off); os = __shfl_xor_sync(0xffffffffu, s0, off);
    nm = fmaxf(m0,om); s0 = s0*__expf(m0-nm) + os*__expf(om-nm); m0 = nm;
    om = __shfl_xor_sync(0xffffffffu, m1, off); os = __shfl_xor_sync(0xffffffffu, s1, off);
    nm = fmaxf(m1,om); s1 = s1*__expf(m1-nm) + os*__expf(om-nm); m1 = nm;
    om = __shfl_xor_sync(0xffffffffu, m2, off); os = __shfl_xor_sync(0xffffffffu, s2, off);
    nm = fmaxf(m2,om); s2 = s2*__expf(m2-nm) + os*__expf(om-nm); m2 = nm;
    om = __shfl_xor_sync(0xffffffffu, m3, off); os = __shfl_xor_sync(0xffffffffu, s3, off);
    nm = fmaxf(m3,om); s3 = s3*__expf(m3-nm) + os*__expf(om-nm); m3 = nm;
  }
  float inv0 = 1.f/(s0+1e-16f), inv1 = 1.f/(s1+1e-16f);
  float inv2 = 1.f/(s2+1e-16f), inv3 = 1.f/(s3+1e-16f);

  // phase B: lane owns columns (lane, lane+32); walk edges sequentially
  bool lo   = lane < 16;
  float mh1 = lo ? m0   : m1,   ih1 = lo ? inv0 : inv1;
  float mh2 = lo ? m2   : m3,   ih2 = lo ? inv2 : inv3;
  float ah1 = lo ? ad.x : ad.y, ah2 = lo ? ad.z : ad.w;
  int c1 = lane, c2 = lane + 32;
  float acc1 = 0.f, acc2 = 0.f;
  for (int i = beg; i < end; i++) {
    int src = g_esrc[i];
    float4 as = *(const float4*)&g_as4[src*4];   // broadcast load
    float a1 = lo ? as.x : as.y;
    float a2 = lo ? as.z : as.w;
    float w1 = __expf(lrelu(a1+ah1) - mh1) * ih1;
    float w2 = __expf(lrelu(a2+ah2) - mh2) * ih2;
    acc1 += w1 * g_h[src*64 + c1];               // coalesced 128B
    acc2 += w2 * g_h[src*64 + c2];               // coalesced 128B
  }
  g_hout[n*64 + c1] = acc1 + gat_b[c1];
  g_hout[n*64 + c2] = acc2 + gat_b[c2];
}

// ---------------- msg_emb = message @ fc_w + fc_b ---------------------------
__global__ void k_msg(const float* __restrict__ msg, const float* __restrict__ fw,
                      const float* __restrict__ fb) {
  int b = blockIdx.x;
  int j = threadIdx.x;   // 64 threads
  const float* mr = msg + b*HIDDEN;
  float acc = fb[j];
  #pragma unroll 8
  for (int k = 0; k < HIDDEN; k++)
    acc += mr[k] * fw[k*64 + j];
  g_msg[b*64 + j] = acc;
}

// ---------------- logits GEMM: out[b,n] = dot(msg[b], hout[n]) --------------
// 128x128 block tile, K=64 resident in smem, 8x8 thread tile, 256 threads.
#define AS_LD 132   // 128 + 4 pad (keeps 16B align, reduces STS conflicts)
__global__ __launch_bounds__(256) void k_gemm(float* __restrict__ out) {
  extern __shared__ float smem[];
  float* As = smem;                // [64][AS_LD]
  float* Bs = smem + 64*AS_LD;     // [64][AS_LD]
  int tid = threadIdx.x;
  int bm  = blockIdx.y * 128;
  int bn  = blockIdx.x * 128;
  int ka  = tid & 63;
  int mg  = tid >> 6;
  #pragma unroll
  for (int j = 0; j < 8; j++) {
    int m0 = j*16 + mg*4;
    float4 v;
    v.x = g_msg[(bm+m0+0)*64 + ka];
    v.y = g_msg[(bm+m0+1)*64 + ka];
    v.z = g_msg[(bm+m0+2)*64 + ka];
    v.w = g_msg[(bm+m0+3)*64 + ka];
    *(float4*)&As[ka*AS_LD + m0] = v;
  }
  #pragma unroll
  for (int j = 0; j < 8; j++) {
    int n0 = j*16 + mg*4;
    int node = bn + n0;
    float4 v = make_float4(0.f,0.f,0.f,0.f);
    if (node + 3 < N_NODES) {
      v.x = g_hout[(node+0)*64 + ka];
      v.y = g_hout[(node+1)*64 + ka];
      v.z = g_hout[(node+2)*64 + ka];
      v.w = g_hout[(node+3)*64 + ka];
    } else {
      if (node+0 < N_NODES) v.x = g_hout[(node+0)*64 + ka];
      if (node+1 < N_NODES) v.y = g_hout[(node+1)*64 + ka];
      if (node+2 < N_NODES) v.z = g_hout[(node+2)*64 + ka];
    }
    *(float4*)&Bs[ka*AS_LD + n0] = v;
  }
  __syncthreads();

  int tx = tid & 15, ty = tid >> 4;
  float acc[8][8];
  #pragma unroll
  for (int i = 0; i < 8; i++)
    #pragma unroll
    for (int j = 0; j < 8; j++) acc[i][j] = 0.f;

  #pragma unroll 8
  for (int k = 0; k < 64; k++) {
    float a[8], b[8];
    *(float4*)&a[0] = *(float4*)&As[k*AS_LD + ty*8];
    *(float4*)&a[4] = *(float4*)&As[k*AS_LD + ty*8 + 4];
    *(float4*)&b[0] = *(float4*)&Bs[k*AS_LD + tx*8];
    *(float4*)&b[4] = *(float4*)&Bs[k*AS_LD + tx*8 + 4];
    #pragma unroll
    for (int i = 0; i < 8; i++)
      #pragma unroll
      for (int j = 0; j < 8; j++)
        acc[i][j] += a[i]*b[j];
  }

  bool full = (bn + 128 <= N_NODES);
  #pragma unroll
  for (int i = 0; i < 8; i++) {
    int row = bm + ty*8 + i;
    float* orow = out + (size_t)row*N_NODES + bn + tx*8;
    if (full) {
      *(float4*)&orow[0] = make_float4(acc[i][0],acc[i][1],acc[i][2],acc[i][3]);
      *(float4*)&orow[4] = make_float4(acc[i][4],acc[i][5],acc[i][6],acc[i][7]);
    } else {
      #pragma unroll
      for (int j = 0; j < 8; j++)
        if (bn + tx*8 + j < N_NODES) orow[j] = acc[i][j];
    }
  }
}

// ---------------- row logsumexp over d_out ----------------------------------
__global__ void k_lse(const float* __restrict__ out) {
  int row = blockIdx.x;
  const float4* p = (const float4*)(out + (size_t)row*N_NODES);
  float m = -1e30f, s = 0.f;
  for (int i = threadIdx.x; i < N_NODES/4; i += 256) {
    float4 v = p[i];
    float lm = fmaxf(fmaxf(v.x,v.y), fmaxf(v.z,v.w));
    if (lm > m) { s *= __expf(m - lm); m = lm; }
    s += __expf(v.x-m) + __expf(v.y-m) + __expf(v.z-m) + __expf(v.w-m);
  }
  __shared__ float sm[256], ss[256];
  int tid = threadIdx.x;
  sm[tid] = m; ss[tid] = s;
  __syncthreads();
  for (int off = 128; off > 0; off >>= 1) {
    if (tid < off) {
      float m2 = sm[tid+off], s2 = ss[tid+off];
      float nm = fmaxf(sm[tid], m2);
      ss[tid] = ss[tid]*__expf(sm[tid]-nm) + s2*__expf(m2-nm);
      sm[tid] = nm;
    }
    __syncthreads();
  }
  if (tid == 0) g_lse[row] = sm[0] + logf(ss[0]);
}

// ---------------- in-place subtract -----------------------------------------
__global__ void k_sub(float* __restrict__ out) {
  int row = blockIdx.y;
  int i   = blockIdx.x*blockDim.x + threadIdx.x;
  if (i < N_NODES/4) {
    float4* p = (float4*)(out + (size_t)row*N_NODES);
    float l = g_lse[row];
    float4 v = p[i];
    v.x -= l; v.y -= l; v.z -= l; v.w -= l;
    p[i] = v;
  }
}

// ---------------- launch -----------------------------------------------------
extern "C" void kernel_launch(void* const* d_in, const int* in_sizes, int n_in,
                              void* d_out, int out_size) {
  const float* message = (const float*)d_in[0];
  const float* x       = (const float*)d_in[1];
  const int*   eidx    = (const int*)  d_in[2];
  const float* gat_w   = (const float*)d_in[3];
  const float* att_src = (const float*)d_in[4];
  const float* att_dst = (const float*)d_in[5];
  const float* gat_b   = (const float*)d_in[6];
  const float* fc_w    = (const float*)d_in[7];
  const float* fc_b    = (const float*)d_in[8];
  float* out = (float*)d_out;

  const int gemm_smem = 2*64*AS_LD*sizeof(float);   // 67584 B
  cudaFuncSetAttribute(k_gemm, cudaFuncAttributeMaxDynamicSharedMemorySize, gemm_smem);

  k_init   <<<(N_NODES+255)/256, 256>>>();
  k_node   <<<N_NODES/4, 256>>>(x, gat_w, att_src, att_dst);
  k_hist   <<<N_EDGES/256, 256>>>(eidx);
  k_scan   <<<1, 1024>>>();
  k_scatter<<<N_EDGES/256, 256>>>(eidx);
  k_agg    <<<(N_NODES*32)/256, 256>>>(gat_b);
  k_msg    <<<BATCH, 64>>>(message, fc_w, fc_b);
  k_gemm   <<<dim3((N_NODES+127)/128, BATCH/128), 256, gemm_smem>>>(out);
  k_lse    <<<BATCH, 256>>>(out);
  k_sub    <<<dim3((N_NODES/4+255)/256, BATCH), 256>>>(out);
}

// round 3
// speedup vs baseline: 1.2915x; 1.2915x over previous
#include <cuda_runtime.h>
#include <cuda_bf16.h>
#include <cstdint>

#define N_NODES 50000
#define N_EDGES 1600000
#define BATCH   1024
#define HIDDEN  256
#define NTN     391              // ceil(50000/128)
#define NB1     49               // ceil(50000/1024)

// ---------------- scratch (device globals) -----------------------------------
__device__ float g_h   [N_NODES*64];
__device__ float g_as4 [N_NODES*4];
__device__ float g_ad4 [N_NODES*4];
__device__ __nv_bfloat16 g_hcat[N_NODES*128];  // [hi(64) | lo(64)] per node
__device__ __nv_bfloat16 g_mcat[BATCH*128];    // [hi(64) | lo(64)] per batch row
__device__ int   g_cnt [N_NODES];
__device__ int   g_off [N_NODES+1];
__device__ int   g_cur [N_NODES];
__device__ int   g_bsum[64];
__device__ int   g_esrc[N_EDGES];
__device__ float g_pmax[BATCH*NTN];
__device__ float g_psum[BATCH*NTN];
__device__ float g_lse [BATCH];

__device__ __forceinline__ float lrelu(float x) { return fmaxf(x, 0.2f*x); }

__device__ __forceinline__ uint32_t smem_u32(const void* p) {
  uint32_t a;
  asm("{ .reg .u64 t; cvta.to.shared.u64 t, %1; cvt.u32.u64 %0, t; }" : "=r"(a) : "l"(p));
  return a;
}
__device__ __forceinline__ void ldm_x4(uint32_t& r0, uint32_t& r1, uint32_t& r2,
                                       uint32_t& r3, uint32_t addr) {
  asm volatile("ldmatrix.sync.aligned.m8n8.x4.shared.b16 {%0,%1,%2,%3}, [%4];"
               : "=r"(r0), "=r"(r1), "=r"(r2), "=r"(r3) : "r"(addr));
}
__device__ __forceinline__ void mma16816(float* c, uint32_t a0, uint32_t a1,
                                         uint32_t a2, uint32_t a3,
                                         uint32_t b0, uint32_t b1) {
  asm volatile(
      "mma.sync.aligned.m16n8k16.row.col.f32.bf16.bf16.f32 "
      "{%0,%1,%2,%3}, {%4,%5,%6,%7}, {%8,%9}, {%0,%1,%2,%3};"
      : "+f"(c[0]), "+f"(c[1]), "+f"(c[2]), "+f"(c[3])
      : "r"(a0), "r"(a1), "r"(a2), "r"(a3), "r"(b0), "r"(b1));
}

// ---------------- init --------------------------------------------------------
__global__ void k_init() {
  int i = blockIdx.x*blockDim.x + threadIdx.x;
  if (i < N_NODES) g_cnt[i] = 0;
}

// ---------------- node transform ----------------------------------------------
__global__ void k_node(const float* __restrict__ x, const float* __restrict__ gw,
                       const float* __restrict__ aw_s, const float* __restrict__ aw_d) {
  __shared__ float sw[256];
  __shared__ float satt[128];
  __shared__ float sx[16];
  int tid = threadIdx.x;
  sw[tid] = gw[tid];
  if (tid < 64)       satt[tid] = aw_s[tid];
  else if (tid < 128) satt[tid] = aw_d[tid-64];
  int n0 = blockIdx.x*4;
  if (tid < 16) sx[tid] = x[n0*4 + tid];
  __syncthreads();
  int local = tid >> 6, j = tid & 63;
  int node = n0 + local;
  float h = sx[local*4+0]*sw[j]     + sx[local*4+1]*sw[64+j]
          + sx[local*4+2]*sw[128+j] + sx[local*4+3]*sw[192+j];
  g_h[node*64 + j] = h;
  float ps = h*satt[j], pd = h*satt[64+j];
  #pragma unroll
  for (int off = 8; off > 0; off >>= 1) {
    ps += __shfl_xor_sync(0xffffffffu, ps, off);
    pd += __shfl_xor_sync(0xffffffffu, pd, off);
  }
  if ((j & 15) == 0) {
    int head = j >> 4;
    g_as4[node*4+head] = ps;
    g_ad4[node*4+head] = pd;
  }
}

// ---------------- CSR build ----------------------------------------------------
__global__ void k_hist(const int* __restrict__ ei) {
  int i = blockIdx.x*blockDim.x + threadIdx.x;
  if (i < N_EDGES) atomicAdd(&g_cnt[ei[N_EDGES + i]], 1);
}

__device__ __forceinline__ int wscan(int v, int lane) {
  #pragma unroll
  for (int off = 1; off < 32; off <<= 1) {
    int t = __shfl_up_sync(0xffffffffu, v, off);
    if (lane >= off) v += t;
  }
  return v;
}

__global__ void k_scan1() {
  __shared__ int wsum[32];
  int tid = threadIdx.x, lane = tid & 31, wid = tid >> 5;
  int i = blockIdx.x*1024 + tid;
  int v = (i < N_NODES) ? g_cnt[i] : 0;
  int incl = wscan(v, lane);
  if (lane == 31) wsum[wid] = incl;
  __syncthreads();
  if (wid == 0) wsum[lane] = wscan(wsum[lane], lane);
  __syncthreads();
  int base = wid ? wsum[wid-1] : 0;
  if (i < N_NODES) g_off[i] = base + incl - v;
  if (tid == 1023) g_bsum[blockIdx.x] = wsum[31];
}

__global__ void k_scan2() {
  int lane = threadIdx.x;
  int a0 = (lane      < NB1) ? g_bsum[lane]      : 0;
  int a1 = (32 + lane < NB1) ? g_bsum[32 + lane] : 0;
  int i0 = wscan(a0, lane);
  int t0 = __shfl_sync(0xffffffffu, i0, 31);
  int i1 = wscan(a1, lane) + t0;
  if (lane      < NB1) g_bsum[lane]      = i0 - a0;
  if (32 + lane < NB1) g_bsum[32 + lane] = i1 - a1;
}

__global__ void k_scan3() {
  int i = blockIdx.x*blockDim.x + threadIdx.x;
  if (i < N_NODES) {
    int o = g_off[i] + g_bsum[i >> 10];
    g_off[i] = o;
    g_cur[i] = o;
  }
  if (i == 0) g_off[N_NODES] = N_EDGES;
}

__global__ void k_scatter(const int* __restrict__ ei) {
  int i = blockIdx.x*blockDim.x + threadIdx.x;
  if (i < N_EDGES) {
    int d = ei[N_EDGES + i];
    int pos = atomicAdd(&g_cur[d], 1);
    g_esrc[pos] = ei[i];
  }
}

// ---------------- per-node softmax + aggregation (one warp / node) ------------
__global__ void k_agg(const float* __restrict__ gat_b) {
  int gwarp = (blockIdx.x*blockDim.x + threadIdx.x) >> 5;
  int lane  = threadIdx.x & 31;
  if (gwarp >= N_NODES) return;
  int n = gwarp;
  int beg = g_off[n], end = g_off[n+1];
  float4 ad = *(const float4*)&g_ad4[n*4];

  float m0=-1e30f,m1=-1e30f,m2=-1e30f,m3=-1e30f;
  float s0=0.f,s1=0.f,s2=0.f,s3=0.f;
  for (int i = beg + lane; i < end; i += 32) {
    int src = g_esrc[i];
    float4 as = *(const float4*)&g_as4[src*4];
    float e0 = lrelu(as.x+ad.x), e1 = lrelu(as.y+ad.y);
    float e2 = lrelu(as.z+ad.z), e3 = lrelu(as.w+ad.w);
    float nm;
    nm = fmaxf(m0,e0); s0 = s0*__expf(m0-nm) + __expf(e0-nm); m0 = nm;
    nm = fmaxf(m1,e1); s1 = s1*__expf(m1-nm) + __expf(e1-nm); m1 = nm;
    nm = fmaxf(m2,e2); s2 = s2*__expf(m2-nm) + __expf(e2-nm); m2 = nm;
    nm = fmaxf(m3,e3); s3 = s3*__expf(m3-nm) + __expf(e3-nm); m3 = nm;
  }
  #pragma unroll
  for (int off = 16; off > 0; off >>= 1) {
    float om, os, nm;
    om = __shfl_xor_sync(0xffffffffu, m0, off); os = __shfl_xor_sync(0xffffffffu, s0, off);
    nm = fmaxf(m0,om); s0 = s0*__expf(m0-nm) + os*__expf(om-nm); m0 = nm;
    om = __shfl_xor_sync(0xffffffffu, m1, off); os = __shfl_xor_sync(0xffffffffu, s1, off);
    nm = fmaxf(m1,om); s1 = s1*__expf(m1-nm) + os*__expf(om-nm); m1 = nm;
    om = __shfl_xor_sync(0xffffffffu, m2, off); os = __shfl_xor_sync(0xffffffffu, s2, off);
    nm = fmaxf(m2,om); s2 = s2*__expf(m2-nm) + os*__expf(om-nm); m2 = nm;
    om = __shfl_xor_sync(0xffffffffu, m3, off); os = __shfl_xor_sync(0xffffffffu, s3, off);
    nm = fmaxf(m3,om); s3 = s3*__expf(m3-nm) + os*__expf(om-nm); m3 = nm;
  }
  float inv0 = 1.f/(s0+1e-16f), inv1 = 1.f/(s1+1e-16f);
  float inv2 = 1.f/(s2+1e-16f), inv3 = 1.f/(s3+1e-16f);

  bool lo = lane < 16;
  float mh1 = lo ? m0 : m1,   ih1 = lo ? inv0 : inv1;
  float mh2 = lo ? m2 : m3,   ih2 = lo ? inv2 : inv3;
  float ah1 = lo ? ad.x : ad.y, ah2 = lo ? ad.z : ad.w;
  int c1 = lane, c2 = lane + 32;
  float acc1 = 0.f, acc2 = 0.f;
  for (int i = beg; i < end; i++) {
    int src = g_esrc[i];
    float4 as = *(const float4*)&g_as4[src*4];
    float a1 = lo ? as.x : as.y;
    float a2 = lo ? as.z : as.w;
    float w1 = __expf(lrelu(a1+ah1) - mh1) * ih1;
    float w2 = __expf(lrelu(a2+ah2) - mh2) * ih2;
    acc1 += w1 * g_h[src*64 + c1];
    acc2 += w2 * g_h[src*64 + c2];
  }
  float v1 = acc1 + gat_b[c1];
  float v2 = acc2 + gat_b[c2];
  __nv_bfloat16 h1 = __float2bfloat16(v1);
  __nv_bfloat16 h2 = __float2bfloat16(v2);
  g_hcat[n*128 + c1]      = h1;
  g_hcat[n*128 + 64 + c1] = __float2bfloat16(v1 - __bfloat162float(h1));
  g_hcat[n*128 + c2]      = h2;
  g_hcat[n*128 + 64 + c2] = __float2bfloat16(v2 - __bfloat162float(h2));
}

// ---------------- msg_emb = message @ fc_w + fc_b (bf16 hi/lo concat) ---------
__global__ void k_msg(const float* __restrict__ msg, const float* __restrict__ fw,
                      const float* __restrict__ fb) {
  int b = blockIdx.x;
  int j = threadIdx.x;   // 64
  const float* mr = msg + b*HIDDEN;
  float acc = fb[j];
  #pragma unroll 8
  for (int k = 0; k < HIDDEN; k++)
    acc += mr[k] * fw[k*64 + j];
  __nv_bfloat16 h = __float2bfloat16(acc);
  g_mcat[b*128 + j]      = h;
  g_mcat[b*128 + 64 + j] = __float2bfloat16(acc - __bfloat162float(h));
}

// ---------------- logits GEMM via mma.sync bf16 (K=128 = hi|lo concat) --------
// Block: 256 threads (8 warps), tile 128(M) x 128(N), K=128 fully in SMEM.
// SMEM tiles: rows padded to 272B (conflict-free ldmatrix). Epilogue stages
// f32 results in SMEM, computes per-tile row (max, sumexp) partials, and does
// coalesced float4 stores.
#define TILE_LD   272                       // bytes per SMEM row (256 + 16 pad)
#define SMEM_DYN  69632                     // 2 * 128 * 272
__global__ __launch_bounds__(256, 1)
void k_gemm(float* __restrict__ out) {
  extern __shared__ char smem[];
  uint32_t sb = smem_u32(smem);
  uint32_t sbA = sb;
  uint32_t sbB = sb + 128*TILE_LD;
  int tid = threadIdx.x, wid = tid >> 5, lid = tid & 31;
  int bm = blockIdx.x * 128;
  int bn = blockIdx.y * 128;
  bool fullTile = (bn + 128 <= N_NODES);

  // ---- load tiles: A (msg) and B (nodes), 128 rows x 256B each ----
  {
    const uint4* srcA = (const uint4*)g_mcat;
    const uint4* srcB = (const uint4*)g_hcat;
    #pragma unroll
    for (int i = tid; i < 2048; i += 256) {
      int row = i >> 4, ch = i & 15;
      // A
      uint4 va = srcA[(size_t)(bm + row)*16 + ch];
      *(uint4*)(smem + row*TILE_LD + ch*16) = va;
      // B
      int node = bn + row;
      uint4 vb = make_uint4(0u,0u,0u,0u);
      if (node < N_NODES) vb = srcB[(size_t)node*16 + ch];
      *(uint4*)(smem + 128*TILE_LD + row*TILE_LD + ch*16) = vb;
    }
  }
  __syncthreads();

  // ---- MMA mainloop: warp tile 64(M) x 32(N), 8 k-steps of 16 ----
  int wm = wid & 1, wn = wid >> 1;
  float acc[4][4][4];
  #pragma unroll
  for (int i = 0; i < 4; i++)
    #pragma unroll
    for (int j = 0; j < 4; j++)
      #pragma unroll
      for (int c = 0; c < 4; c++) acc[i][j][c] = 0.f;

  #pragma unroll
  for (int ks = 0; ks < 8; ks++) {
    uint32_t a[4][4];
    #pragma unroll
    for (int mf = 0; mf < 4; mf++) {
      uint32_t addr = sbA + (wm*64 + mf*16 + (lid & 15))*TILE_LD
                          + ks*32 + (lid >> 4)*16;
      ldm_x4(a[mf][0], a[mf][1], a[mf][2], a[mf][3], addr);
    }
    uint32_t b[4][2];
    #pragma unroll
    for (int nfp = 0; nfp < 2; nfp++) {
      uint32_t addr = sbB + (wn*32 + nfp*16 + ((lid >> 4) & 1)*8 + (lid & 7))*TILE_LD
                          + ks*32 + ((lid >> 3) & 1)*16;
      uint32_t r0, r1, r2, r3;
      ldm_x4(r0, r1, r2, r3, addr);
      b[nfp*2][0] = r0; b[nfp*2][1] = r1;
      b[nfp*2+1][0] = r2; b[nfp*2+1][1] = r3;
    }
    #pragma unroll
    for (int mf = 0; mf < 4; mf++)
      #pragma unroll
      for (int nf = 0; nf < 4; nf++)
        mma16816(acc[mf][nf], a[mf][0], a[mf][1], a[mf][2], a[mf][3],
                 b[nf][0], b[nf][1]);
  }

  // ---- stage accumulators to SMEM (f32 [128][132]) ----
  __syncthreads();
  float* epi = (float*)smem;
  int r0 = lid >> 2, c0 = (lid & 3)*2;
  #pragma unroll
  for (int mf = 0; mf < 4; mf++) {
    int srow = wm*64 + mf*16;
    #pragma unroll
    for (int nf = 0; nf < 4; nf++) {
      int scol = wn*32 + nf*8 + c0;
      *(float2*)&epi[(srow + r0    )*132 + scol] = make_float2(acc[mf][nf][0], acc[mf][nf][1]);
      *(float2*)&epi[(srow + r0 + 8)*132 + scol] = make_float2(acc[mf][nf][2], acc[mf][nf][3]);
    }
  }
  __syncthreads();

  // ---- epilogue: per-row lse partials + coalesced store (16 rows per warp) ----
  for (int r = 0; r < 16; r++) {
    int row = wid*16 + r;
    float4 v = *(float4*)&epi[row*132 + lid*4];
    int col = bn + lid*4;
    float x0 = v.x, x1 = v.y, x2 = v.z, x3 = v.w;
    if (!fullTile) {
      if (col+0 >= N_NODES) x0 = -1e30f;
      if (col+1 >= N_NODES) x1 = -1e30f;
      if (col+2 >= N_NODES) x2 = -1e30f;
      if (col+3 >= N_NODES) x3 = -1e30f;
    }
    float m = fmaxf(fmaxf(x0, x1), fmaxf(x2, x3));
    #pragma unroll
    for (int off = 16; off > 0; off >>= 1)
      m = fmaxf(m, __shfl_xor_sync(0xffffffffu, m, off));
    float s = __expf(x0-m) + __expf(x1-m) + __expf(x2-m) + __expf(x3-m);
    #pragma unroll
    for (int off = 16; off > 0; off >>= 1)
      s += __shfl_xor_sync(0xffffffffu, s, off);
    if (lid == 0) {
      g_pmax[(size_t)(bm+row)*NTN + blockIdx.y] = m;
      g_psum[(size_t)(bm+row)*NTN + blockIdx.y] = s;
    }
    float* op = out + (size_t)(bm+row)*N_NODES + col;
    if (fullTile) {
      *(float4*)op = v;
    } else {
      if (col+0 < N_NODES) op[0] = v.x;
      if (col+1 < N_NODES) op[1] = v.y;
      if (col+2 < N_NODES) op[2] = v.z;
      if (col+3 < N_NODES) op[3] = v.w;
    }
  }
}

// ---------------- final lse from partials --------------------------------------
__global__ void k_lse() {   // grid 128, block 256 (8 warps) -> 1024 rows
  int wid = threadIdx.x >> 5, lid = threadIdx.x & 31;
  int row = blockIdx.x*8 + wid;
  float m = -1e30f, s = 0.f;
  for (int i = lid; i < NTN; i += 32) {
    float mi = g_pmax[(size_t)row*NTN + i];
    float si = g_psum[(size_t)row*NTN + i];
    float nm = fmaxf(m, mi);
    s = s*__expf(m - nm) + si*__expf(mi - nm);
    m = nm;
  }
  #pragma unroll
  for (int off = 16; off > 0; off >>= 1) {
    float om = __shfl_xor_sync(0xffffffffu, m, off);
    float os = __shfl_xor_sync(0xffffffffu, s, off);
    float nm = fmaxf(m, om);
    s = s*__expf(m - nm) + os*__expf(om - nm);
    m = nm;
  }
  if (lid == 0) g_lse[row] = m + logf(s);
}

// ---------------- in-place subtract --------------------------------------------
__global__ void k_sub(float* __restrict__ out) {
  int row = blockIdx.y;
  int i = blockIdx.x*blockDim.x + threadIdx.x;
  if (i < N_NODES/4) {
    float4* p = (float4*)(out + (size_t)row*N_NODES);
    float l = g_lse[row];
    float4 v = p[i];
    v.x -= l; v.y -= l; v.z -= l; v.w -= l;
    p[i] = v;
  }
}

// ---------------- launch --------------------------------------------------------
extern "C" void kernel_launch(void* const* d_in, const int* in_sizes, int n_in,
                              void* d_out, int out_size) {
  const float* message = (const float*)d_in[0];
  const float* x       = (const float*)d_in[1];
  const int*   eidx    = (const int*)  d_in[2];
  const float* gat_w   = (const float*)d_in[3];
  const float* att_src = (const float*)d_in[4];
  const float* att_dst = (const float*)d_in[5];
  const float* gat_b   = (const float*)d_in[6];
  const float* fc_w    = (const float*)d_in[7];
  const float* fc_b    = (const float*)d_in[8];
  float* out = (float*)d_out;

  cudaFuncSetAttribute(k_gemm, cudaFuncAttributeMaxDynamicSharedMemorySize, SMEM_DYN);

  k_init   <<<(N_NODES+255)/256, 256>>>();
  k_node   <<<N_NODES/4, 256>>>(x, gat_w, att_src, att_dst);
  k_msg    <<<BATCH, 64>>>(message, fc_w, fc_b);
  k_hist   <<<N_EDGES/256, 256>>>(eidx);
  k_scan1  <<<NB1, 1024>>>();
  k_scan2  <<<1, 32>>>();
  k_scan3  <<<(N_NODES+255)/256, 256>>>();
  k_scatter<<<N_EDGES/256, 256>>>(eidx);
  k_agg    <<<(N_NODES*32)/256, 256>>>(gat_b);
  k_gemm   <<<dim3(BATCH/128, NTN), 256, SMEM_DYN>>>(out);
  k_lse    <<<BATCH/8, 256>>>();
  k_sub    <<<dim3((N_NODES/4+255)/256, BATCH), 256>>>(out);
}